// round 1
// baseline (speedup 1.0000x reference)
#include <cuda_runtime.h>

#define N 8192
#define BB 2
#define CH 64
#define KNB 16
#define FULLMASK 0xffffffffu

// ---------------- scratch (static device globals; no allocation) ----------------
__device__ float g_q1[BB*N*CH];
__device__ float g_q2[BB*N*CH];
__device__ float g_r1[BB*N*CH];
__device__ float g_r2[BB*N*CH];
__device__ float g_c1[BB*N*CH];
__device__ float g_c2[BB*N*CH];
__device__ float g_f1[BB*N*CH];
__device__ float g_f2[BB*N*CH];
__device__ int   g_i12[BB*N*KNB];
__device__ int   g_i21[BB*N*KNB];

__device__ __forceinline__ float leaky(float x) { return x > 0.0f ? x : 0.1f * x; }

// ---------------- feature transform: out[b,n,m] = sum_c feat[b,c,n]*W[m,c] + bias[m] ----------------
__global__ void transform_kernel(const float* __restrict__ feat,
                                 const float* __restrict__ W,
                                 const float* __restrict__ bias,
                                 float* __restrict__ out)
{
    __shared__ float s_wt[64 * 65];
    __shared__ float s_f[64 * 32];
    const int b = blockIdx.y;
    const int n0 = blockIdx.x * 32;
    const int tid = threadIdx.x;
    for (int i = tid; i < 64 * 64; i += 256) {
        int m = i >> 6, c = i & 63;
        s_wt[c * 65 + m] = W[i];
    }
    for (int i = tid; i < 64 * 32; i += 256) {
        int c = i >> 5, np = i & 31;
        s_f[i] = feat[((b * 64 + c) * N) + n0 + np];
    }
    __syncthreads();
    const int m = tid & 63, grp = tid >> 6;
    const float bv = bias[m];
    for (int t = 0; t < 8; t++) {
        int np = grp * 8 + t;
        float acc = bv;
        #pragma unroll
        for (int c = 0; c < 64; c++)
            acc += s_f[c * 32 + np] * s_wt[c * 65 + m];
        out[((b * N) + n0 + np) * 64 + m] = acc;
    }
}

// ---------------- brute-force KNN (warp-collective sorted top-16) ----------------
#define TILE 2048
__global__ void knn_kernel(const float* __restrict__ pc1, const float* __restrict__ pc2,
                           int* __restrict__ i12, int* __restrict__ i21)
{
    __shared__ float s_x[TILE], s_y[TILE], s_z[TILE];
    const int dir = blockIdx.z;
    const float* q  = dir ? pc2 : pc1;
    const float* db = dir ? pc1 : pc2;
    int* oi = dir ? i21 : i12;
    const int b = blockIdx.y;
    const int warp = threadIdx.x >> 5, lane = threadIdx.x & 31;
    const int n = blockIdx.x * 16 + warp;
    const float* qb = q + b * 3 * N;
    const float qx = qb[n], qy = qb[N + n], qz = qb[2 * N + n];
    const float* dbb = db + b * 3 * N;

    // warp-distributed sorted list (ascending); lanes 0..15 = true top-16
    float bd = 3.0e38f;
    int bi = 0;

    for (int t = 0; t < N; t += TILE) {
        __syncthreads();
        for (int i = threadIdx.x; i < TILE; i += 512) {
            s_x[i] = dbb[t + i];
            s_y[i] = dbb[N + t + i];
            s_z[i] = dbb[2 * N + t + i];
        }
        __syncthreads();
        for (int p = 0; p < TILE; p += 32) {
            int j = p + lane;
            float dx = s_x[j] - qx, dy = s_y[j] - qy, dz = s_z[j] - qz;
            float d = dx * dx + dy * dy + dz * dz;
            float tau = __shfl_sync(FULLMASK, bd, 15);   // current 16th smallest
            unsigned msk = __ballot_sync(FULLMASK, d < tau);
            while (msk) {
                int src = __ffs(msk) - 1;
                msk &= msk - 1;
                float dd = __shfl_sync(FULLMASK, d, src);
                int jj = t + p + src;
                float up = __shfl_up_sync(FULLMASK, bd, 1);
                int  upi = __shfl_up_sync(FULLMASK, bi, 1);
                if (lane == 0) up = -1.0f;  // distances >= 0, acts as -inf
                if (bd > dd) {
                    bool take_up = up > dd;
                    bd = take_up ? up : dd;
                    bi = take_up ? upi : jj;
                }
            }
        }
    }
    if (lane < 16) oi[((b * N) + n) * 16 + lane] = bi;
}

// ---------------- fused cross: gather + pos-conv + (1 or 2) MLP layers + maxpool ----------------
// block = 256 threads = 8 warps, 1 warp per query, 8 queries per warp.
// lane c owns output channels c and c+32; all K=16 neighbors batched per matmul.
template <int NL>
__global__ void cross_kernel(const int* __restrict__ idx,
                             const float* __restrict__ xyz1, const float* __restrict__ xyz2,
                             const float* __restrict__ p1, const float* __restrict__ p2,
                             const float* __restrict__ posw, const float* __restrict__ posb,
                             const float* __restrict__ w1, const float* __restrict__ b1,
                             const float* __restrict__ w2, const float* __restrict__ b2,
                             float* __restrict__ out, int transposed)
{
    extern __shared__ float sm[];
    float* s_w1  = sm;           // 4096: [(jb*64+c)*4+u] = w1[c*64 + jb*4+u]
    float* s_w2  = sm + 4096;    // 4096
    float* s_pwt = sm + 8192;    // 192: [d*64+c] = posw[c*3+d]
    float* s_pb  = sm + 8384;    // 64
    float* s_b1  = sm + 8448;    // 64
    float* s_b2  = sm + 8512;    // 64
    float* s_h   = sm + 8576;    // 8 warps * 16k * 64 = 8192 (k-major per warp)

    const int tid = threadIdx.x;
    for (int i = tid; i < 4096; i += 256) {
        int jb = i >> 8, c = (i >> 2) & 63, u = i & 3;
        s_w1[i] = w1[c * 64 + jb * 4 + u];
        if (NL == 2) s_w2[i] = w2[c * 64 + jb * 4 + u];
    }
    if (tid < 192) s_pwt[tid] = posw[(tid & 63) * 3 + (tid >> 6)];
    if (tid < 64) {
        s_pb[tid] = posb[tid];
        s_b1[tid] = b1[tid];
        if (NL == 2) s_b2[tid] = b2[tid];
    }
    __syncthreads();

    const int warp = tid >> 5, lane = tid & 31;
    float* sh = s_h + warp * 1024;
    const int wq0 = (blockIdx.x * 8 + warp) * 8;

    for (int qi = 0; qi < 8; qi++) {
        const int q = wq0 + qi;
        const int b = q >> 13, n = q & (N - 1);
        int myidx = idx[q * 16 + (lane & 15)];
        const float p1a = p1[q * 64 + lane];
        const float p1b = p1[q * 64 + 32 + lane];
        const float* x1b = xyz1 + b * 3 * N;
        const float qx = x1b[n], qy = x1b[N + n], qz = x1b[2 * N + n];
        const float* x2b = xyz2 + b * 3 * N;

        // phase 0: h[k][c] = leaky(g2 + p1 + posf)
        #pragma unroll
        for (int k = 0; k < 16; k++) {
            int j = __shfl_sync(FULLMASK, myidx, k);
            float dx = x2b[j] - qx, dy = x2b[N + j] - qy, dz = x2b[2 * N + j] - qz;
            const float* p2r = p2 + ((size_t)((b << 13) + j)) * 64;
            float ga = p2r[lane], gb = p2r[lane + 32];
            float pa = s_pb[lane]      + dx * s_pwt[lane]      + dy * s_pwt[64 + lane]  + dz * s_pwt[128 + lane];
            float pb = s_pb[lane + 32] + dx * s_pwt[lane + 32] + dy * s_pwt[96 + lane]  + dz * s_pwt[160 + lane];
            sh[k * 64 + lane]      = leaky(ga + p1a + pa);
            sh[k * 64 + 32 + lane] = leaky(gb + p1b + pb);
        }
        __syncwarp();

        float ya[16], yb[16];
        // ----- layer 1 -----
        #pragma unroll
        for (int k = 0; k < 16; k++) { ya[k] = s_b1[lane]; yb[k] = s_b1[lane + 32]; }
        #pragma unroll
        for (int jb = 0; jb < 16; jb++) {
            float4 wa = *(const float4*)(s_w1 + (jb * 64 + lane) * 4);
            float4 wb = *(const float4*)(s_w1 + (jb * 64 + lane + 32) * 4);
            #pragma unroll
            for (int k = 0; k < 16; k++) {
                float4 hv = *(const float4*)(sh + k * 64 + jb * 4);
                ya[k] += hv.x * wa.x + hv.y * wa.y + hv.z * wa.z + hv.w * wa.w;
                yb[k] += hv.x * wb.x + hv.y * wb.y + hv.z * wb.z + hv.w * wb.w;
            }
        }
        #pragma unroll
        for (int k = 0; k < 16; k++) { ya[k] = leaky(ya[k]); yb[k] = leaky(yb[k]); }

        if (NL == 2) {
            __syncwarp();
            #pragma unroll
            for (int k = 0; k < 16; k++) { sh[k * 64 + lane] = ya[k]; sh[k * 64 + 32 + lane] = yb[k]; }
            __syncwarp();
            #pragma unroll
            for (int k = 0; k < 16; k++) { ya[k] = s_b2[lane]; yb[k] = s_b2[lane + 32]; }
            #pragma unroll
            for (int jb = 0; jb < 16; jb++) {
                float4 wa = *(const float4*)(s_w2 + (jb * 64 + lane) * 4);
                float4 wb = *(const float4*)(s_w2 + (jb * 64 + lane + 32) * 4);
                #pragma unroll
                for (int k = 0; k < 16; k++) {
                    float4 hv = *(const float4*)(sh + k * 64 + jb * 4);
                    ya[k] += hv.x * wa.x + hv.y * wa.y + hv.z * wa.z + hv.w * wa.w;
                    yb[k] += hv.x * wb.x + hv.y * wb.y + hv.z * wb.z + hv.w * wb.w;
                }
            }
            #pragma unroll
            for (int k = 0; k < 16; k++) { ya[k] = leaky(ya[k]); yb[k] = leaky(yb[k]); }
        }

        float ma = -3.0e38f, mb = -3.0e38f;
        #pragma unroll
        for (int k = 0; k < 16; k++) { ma = fmaxf(ma, ya[k]); mb = fmaxf(mb, yb[k]); }

        if (transposed) {
            out[((b * 64) + lane) * N + n] = ma;
            out[((b * 64) + lane + 32) * N + n] = mb;
        } else {
            out[q * 64 + lane] = ma;
            out[q * 64 + 32 + lane] = mb;
        }
        __syncwarp();
    }
}

// ---------------- final linear: writes [B,N,64] scratch AND transposed [B,64,N] output ----------------
__global__ void final_linear_kernel(const float* __restrict__ x,
                                    const float* __restrict__ W,
                                    const float* __restrict__ bias,
                                    float* __restrict__ out_bn,
                                    float* __restrict__ out_cn)
{
    __shared__ float s_wt[64 * 65];
    __shared__ float s_x[32 * 64];
    const int tid = threadIdx.x;
    const int q0 = blockIdx.x * 32;
    for (int i = tid; i < 64 * 64; i += 256) {
        int m = i >> 6, c = i & 63;
        s_wt[c * 65 + m] = W[i];
    }
    for (int i = tid; i < 2048; i += 256)
        s_x[i] = x[q0 * 64 + i];
    __syncthreads();
    const int m = tid & 63, grp = tid >> 6;
    const float bv = bias[m];
    for (int t = 0; t < 8; t++) {
        int np = grp * 8 + t;
        float acc = bv;
        #pragma unroll
        for (int c = 0; c < 64; c++)
            acc += s_x[np * 64 + c] * s_wt[c * 65 + m];
        int q = q0 + np;
        int b = q >> 13, n = q & (N - 1);
        out_bn[q * 64 + m] = acc;
        out_cn[((b * 64) + m) * N + n] = acc;
    }
}

// ---------------- launch ----------------
extern "C" void kernel_launch(void* const* d_in, const int* in_sizes, int n_in,
                              void* d_out, int out_size)
{
    const float* pc1     = (const float*)d_in[0];
    const float* pc2     = (const float*)d_in[1];
    const float* feat1   = (const float*)d_in[2];
    const float* feat2   = (const float*)d_in[3];
    const float* t11_w   = (const float*)d_in[4];
    const float* t11_b   = (const float*)d_in[5];
    const float* t22_w   = (const float*)d_in[6];
    const float* t22_b   = (const float*)d_in[7];
    const float* pos1_w  = (const float*)d_in[8];
    const float* pos1_b  = (const float*)d_in[9];
    const float* mlp1_w1 = (const float*)d_in[10];
    const float* mlp1_b1 = (const float*)d_in[11];
    const float* mlp1_w2 = (const float*)d_in[12];
    const float* mlp1_b2 = (const float*)d_in[13];
    const float* t1_w    = (const float*)d_in[14];
    const float* t1_b    = (const float*)d_in[15];
    const float* t2_w    = (const float*)d_in[16];
    const float* t2_b    = (const float*)d_in[17];
    const float* pos2_w  = (const float*)d_in[18];
    const float* pos2_b  = (const float*)d_in[19];
    const float* mlp2_w1 = (const float*)d_in[20];
    const float* mlp2_b1 = (const float*)d_in[21];
    float* out = (float*)d_out;

    float *q1, *q2, *r1, *r2, *c1, *c2, *f1, *f2;
    int *i12, *i21;
    cudaGetSymbolAddress((void**)&q1, g_q1);
    cudaGetSymbolAddress((void**)&q2, g_q2);
    cudaGetSymbolAddress((void**)&r1, g_r1);
    cudaGetSymbolAddress((void**)&r2, g_r2);
    cudaGetSymbolAddress((void**)&c1, g_c1);
    cudaGetSymbolAddress((void**)&c2, g_c2);
    cudaGetSymbolAddress((void**)&f1, g_f1);
    cudaGetSymbolAddress((void**)&f2, g_f2);
    cudaGetSymbolAddress((void**)&i12, g_i12);
    cudaGetSymbolAddress((void**)&i21, g_i21);

    // pre-transforms
    transform_kernel<<<dim3(N / 32, BB), 256>>>(feat1, t11_w, t11_b, q1);
    transform_kernel<<<dim3(N / 32, BB), 256>>>(feat2, t22_w, t22_b, q2);
    transform_kernel<<<dim3(N / 32, BB), 256>>>(feat2, t11_w, t11_b, r1);
    transform_kernel<<<dim3(N / 32, BB), 256>>>(feat1, t22_w, t22_b, r2);

    // bidirectional KNN
    knn_kernel<<<dim3(N / 16, BB, 2), 512>>>(pc1, pc2, i12, i21);

    const size_t smem = (size_t)(4096 + 4096 + 192 + 64 + 64 + 64 + 8 * 1024) * sizeof(float);
    cudaFuncSetAttribute(cross_kernel<2>, cudaFuncAttributeMaxDynamicSharedMemorySize, (int)smem);
    cudaFuncSetAttribute(cross_kernel<1>, cudaFuncAttributeMaxDynamicSharedMemorySize, (int)smem);

    // cross 1 & 2 (2 mlp layers each)
    cross_kernel<2><<<BB * N / 64, 256, smem>>>(i12, pc1, pc2, q1, q2, pos1_w, pos1_b,
                                                mlp1_w1, mlp1_b1, mlp1_w2, mlp1_b2, c1, 0);
    cross_kernel<2><<<BB * N / 64, 256, smem>>>(i21, pc2, pc1, r1, r2, pos1_w, pos1_b,
                                                mlp1_w1, mlp1_b1, mlp1_w2, mlp1_b2, c2, 0);

    // fn1, fn2: final linears (write output region 0 and 1, plus [B,N,64] scratch for cross3)
    final_linear_kernel<<<BB * N / 32, 256>>>(c1, t1_w, t1_b, f1, out);
    final_linear_kernel<<<BB * N / 32, 256>>>(c2, t2_w, t2_b, f2, out + (size_t)BB * 64 * N);

    // cross 3 (1 mlp layer), writes transposed directly to output region 2
    cross_kernel<1><<<BB * N / 64, 256, smem>>>(i12, pc1, pc2, f1, f2, pos2_w, pos2_b,
                                                mlp2_w1, mlp2_b1, mlp2_w1, mlp2_b1,
                                                out + (size_t)2 * BB * 64 * N, 1);
}

// round 2
// speedup vs baseline: 1.3289x; 1.3289x over previous
#include <cuda_runtime.h>

#define N 8192
#define BB 2
#define CH 64
#define KNB 16
#define FULLMASK 0xffffffffu
typedef unsigned long long ull;

// ---------------- scratch (static device globals; no allocation) ----------------
__device__ float g_q1[BB*N*CH];
__device__ float g_q2[BB*N*CH];
__device__ float g_r1[BB*N*CH];
__device__ float g_r2[BB*N*CH];
__device__ float g_c1[BB*N*CH];
__device__ float g_c2[BB*N*CH];
__device__ float g_f1[BB*N*CH];
__device__ float g_f2[BB*N*CH];
__device__ int   g_i12[BB*N*KNB];
__device__ int   g_i21[BB*N*KNB];

__device__ __forceinline__ float leaky(float x) { return fmaxf(x, 0.1f * x); }

// ---------------- packed f32x2 helpers ----------------
__device__ __forceinline__ ull ffma2(ull a, ull b, ull c) {
    ull d; asm("fma.rn.f32x2 %0, %1, %2, %3;" : "=l"(d) : "l"(a), "l"(b), "l"(c)); return d;
}
__device__ __forceinline__ ull fmul2(ull a, ull b) {
    ull d; asm("mul.rn.f32x2 %0, %1, %2;" : "=l"(d) : "l"(a), "l"(b)); return d;
}
__device__ __forceinline__ ull fadd2(ull a, ull b) {
    ull d; asm("add.rn.f32x2 %0, %1, %2;" : "=l"(d) : "l"(a), "l"(b)); return d;
}
__device__ __forceinline__ ull pk2(float x, float y) {
    ull r; asm("mov.b64 %0, {%1, %2};" : "=l"(r) : "f"(x), "f"(y)); return r;
}
__device__ __forceinline__ ull dup2(float x) {
    ull r; asm("mov.b64 %0, {%1, %1};" : "=l"(r) : "f"(x)); return r;
}
__device__ __forceinline__ void unpk2(float& lo, float& hi, ull v) {
    asm("mov.b64 {%0, %1}, %2;" : "=f"(lo), "=f"(hi) : "l"(v));
}
__device__ __forceinline__ ull lky2(ull v) {
    float a, b; unpk2(a, b, v);
    return pk2(fmaxf(a, 0.1f * a), fmaxf(b, 0.1f * b));
}

// ---------------- fused 4-way feature transform ----------------
__global__ __launch_bounds__(256) void transform4_kernel(
    const float* __restrict__ f1g, const float* __restrict__ f2g,
    const float* __restrict__ w11, const float* __restrict__ b11,
    const float* __restrict__ w22, const float* __restrict__ b22,
    float* __restrict__ q1, float* __restrict__ q2,
    float* __restrict__ r1, float* __restrict__ r2)
{
    __shared__ ull s_wp[64 * 64];   // [c][m] = (w11[m][c], w22[m][c])
    __shared__ ull s_f12[64 * 32];  // [c][np] = (f1, f2)
    __shared__ ull s_f21[64 * 32];  // [c][np] = (f2, f1)
    const int b = blockIdx.y, n0 = blockIdx.x * 32, tid = threadIdx.x;

    for (int i = tid; i < 4096; i += 256) {
        int m = i >> 6, c = i & 63;
        s_wp[c * 64 + m] = pk2(w11[i], w22[i]);
    }
    for (int i = tid; i < 2048; i += 256) {
        int c = i >> 5, np = i & 31;
        float a = f1g[(b * 64 + c) * N + n0 + np];
        float d = f2g[(b * 64 + c) * N + n0 + np];
        s_f12[i] = pk2(a, d);
        s_f21[i] = pk2(d, a);
    }
    __syncthreads();

    const int m = tid & 63, grp = tid >> 6;
    ull bq = pk2(b11[m], b22[m]);
    ull accq[8], accr[8];
    #pragma unroll
    for (int t = 0; t < 8; t++) { accq[t] = bq; accr[t] = bq; }

    #pragma unroll 4
    for (int c = 0; c < 64; c++) {
        ull wv = s_wp[c * 64 + m];
        #pragma unroll
        for (int t = 0; t < 8; t++) {
            int np = grp * 8 + t;
            accq[t] = ffma2(s_f12[c * 32 + np], wv, accq[t]);
            accr[t] = ffma2(s_f21[c * 32 + np], wv, accr[t]);
        }
    }
    #pragma unroll
    for (int t = 0; t < 8; t++) {
        int q = b * N + n0 + grp * 8 + t;
        float v1, v2;
        unpk2(v1, v2, accq[t]); q1[q * 64 + m] = v1; q2[q * 64 + m] = v2;
        unpk2(v1, v2, accr[t]); r1[q * 64 + m] = v1; r2[q * 64 + m] = v2;
    }
}

// ---------------- brute-force KNN ----------------
#define TILE 2048
__device__ __forceinline__ void knn_insert(float& bd, int& bi, float dd, int jj, int lane) {
    float up = __shfl_up_sync(FULLMASK, bd, 1);
    int  upi = __shfl_up_sync(FULLMASK, bi, 1);
    if (lane == 0) up = -1.0f;
    if (bd > dd) {
        bool tk = up > dd;
        bd = tk ? up : dd;
        bi = tk ? upi : jj;
    }
}

__global__ __launch_bounds__(512) void knn_kernel(const float* __restrict__ pc1,
                                                  const float* __restrict__ pc2,
                                                  int* __restrict__ i12, int* __restrict__ i21)
{
    __shared__ float2 s_x[TILE / 2], s_y[TILE / 2], s_z[TILE / 2];
    const int dir = blockIdx.z;
    const float* q  = dir ? pc2 : pc1;
    const float* db = dir ? pc1 : pc2;
    int* oi = dir ? i21 : i12;
    const int b = blockIdx.y;
    const int warp = threadIdx.x >> 5, lane = threadIdx.x & 31;
    const int n = blockIdx.x * 16 + warp;
    const float* qb = q + b * 3 * N;
    const ull nqx = dup2(-qb[n]);
    const ull nqy = dup2(-qb[N + n]);
    const ull nqz = dup2(-qb[2 * N + n]);
    const float* dbb = db + b * 3 * N;

    float bd = 3.0e38f;
    int bi = 0;
    float tau = 3.0e38f;

    for (int t = 0; t < N; t += TILE) {
        __syncthreads();
        const float2* gx = (const float2*)(dbb + t);
        const float2* gy = (const float2*)(dbb + N + t);
        const float2* gz = (const float2*)(dbb + 2 * N + t);
        for (int i = threadIdx.x; i < TILE / 2; i += 512) {
            s_x[i] = gx[i]; s_y[i] = gy[i]; s_z[i] = gz[i];
        }
        __syncthreads();
        for (int p2 = 0; p2 < TILE / 2; p2 += 32) {
            ull xv = *(const ull*)&s_x[p2 + lane];
            ull yv = *(const ull*)&s_y[p2 + lane];
            ull zv = *(const ull*)&s_z[p2 + lane];
            ull dx = fadd2(xv, nqx);
            ull dy = fadd2(yv, nqy);
            ull dz = fadd2(zv, nqz);
            ull d2 = fmul2(dx, dx);
            d2 = ffma2(dy, dy, d2);
            d2 = ffma2(dz, dz, d2);
            float d0, d1; unpk2(d0, d1, d2);
            unsigned m0 = __ballot_sync(FULLMASK, d0 < tau);
            unsigned m1 = __ballot_sync(FULLMASK, d1 < tau);
            if (m0 | m1) {
                const int base = t + 2 * p2;
                while (m0) {
                    int src = __ffs(m0) - 1; m0 &= m0 - 1;
                    float dd = __shfl_sync(FULLMASK, d0, src);
                    knn_insert(bd, bi, dd, base + 2 * src, lane);
                }
                while (m1) {
                    int src = __ffs(m1) - 1; m1 &= m1 - 1;
                    float dd = __shfl_sync(FULLMASK, d1, src);
                    knn_insert(bd, bi, dd, base + 2 * src + 1, lane);
                }
                tau = __shfl_sync(FULLMASK, bd, 15);
            }
        }
    }
    if (lane < 16) oi[((b * N) + n) * 16 + lane] = bi;
}

// ---------------- fused cross ----------------
template <int NL>
__global__ __launch_bounds__(256) void cross_kernel(
    const int* __restrict__ iA, const int* __restrict__ iB,
    const float* __restrict__ xA, const float* __restrict__ xB,
    const float* __restrict__ p1A, const float* __restrict__ p2A,
    const float* __restrict__ p1B, const float* __restrict__ p2B,
    const float* __restrict__ posw, const float* __restrict__ posb,
    const float* __restrict__ w1, const float* __restrict__ b1,
    const float* __restrict__ w2, const float* __restrict__ b2,
    float* __restrict__ outA, float* __restrict__ outB, int transposed)
{
    extern __shared__ float sm[];
    float* s_w1  = sm;
    float* s_w2  = sm + 4096;
    float* s_pwt = sm + 8192;
    float* s_pb  = sm + 8384;
    float* s_b1  = sm + 8448;
    float* s_b2  = sm + 8512;
    ull*   s_hp  = (ull*)(sm + 8576);

    const int dir = blockIdx.y;
    const int* idx = dir ? iB : iA;
    const float* xyz1 = dir ? xB : xA;
    const float* xyz2 = dir ? xA : xB;
    const float* p1 = dir ? p1B : p1A;
    const float* p2 = dir ? p2B : p2A;
    float* out = dir ? outB : outA;

    const int tid = threadIdx.x;
    for (int i = tid; i < 4096; i += 256) {
        int jb = i >> 8, c = (i >> 2) & 63, u = i & 3;
        s_w1[i] = w1[c * 64 + jb * 4 + u];
        if (NL == 2) s_w2[i] = w2[c * 64 + jb * 4 + u];
    }
    if (tid < 192) s_pwt[tid] = posw[(tid & 63) * 3 + (tid >> 6)];
    if (tid < 64) {
        s_pb[tid] = posb[tid];
        s_b1[tid] = b1[tid];
        if (NL == 2) s_b2[tid] = b2[tid];
    }
    __syncthreads();

    const int warp = tid >> 5, lane = tid & 31;
    ull* shp = s_hp + warp * 512;
    const int wq0 = (blockIdx.x * 8 + warp) * 8;

    const float pw0a = s_pwt[lane],      pw1a = s_pwt[64 + lane],  pw2a = s_pwt[128 + lane];
    const float pw0b = s_pwt[lane + 32], pw1b = s_pwt[96 + lane],  pw2b = s_pwt[160 + lane];
    const float pba = s_pb[lane], pbb = s_pb[lane + 32];
    const ull bd1a = dup2(s_b1[lane]), bd1b = dup2(s_b1[lane + 32]);
    const ull bd2a = (NL == 2) ? dup2(s_b2[lane]) : 0ull;
    const ull bd2b = (NL == 2) ? dup2(s_b2[lane + 32]) : 0ull;

    for (int qi = 0; qi < 8; qi++) {
        const int q = wq0 + qi;
        const int b = q >> 13, n = q & (N - 1);
        const int myidx = idx[q * 16 + (lane & 15)];
        const float p1a = p1[q * 64 + lane];
        const float p1b = p1[q * 64 + 32 + lane];
        const float* x1b = xyz1 + b * 3 * N;
        const float qx = x1b[n], qy = x1b[N + n], qz = x1b[2 * N + n];
        const float* x2b = xyz2 + b * 3 * N;
        const float nx = x2b[myidx], ny = x2b[N + myidx], nz = x2b[2 * N + myidx];

        float pva = 0.f, pvb = 0.f;
        #pragma unroll
        for (int k = 0; k < 16; k++) {
            int j = __shfl_sync(FULLMASK, myidx, k);
            float dx = __shfl_sync(FULLMASK, nx, k) - qx;
            float dy = __shfl_sync(FULLMASK, ny, k) - qy;
            float dz = __shfl_sync(FULLMASK, nz, k) - qz;
            const float* p2r = p2 + ((size_t)((b << 13) + j)) * 64;
            float ga = p2r[lane], gb = p2r[lane + 32];
            float pa = pba + dx * pw0a + dy * pw1a + dz * pw2a;
            float pb = pbb + dx * pw0b + dy * pw1b + dz * pw2b;
            float ha = leaky(ga + p1a + pa);
            float hb = leaky(gb + p1b + pb);
            if (k & 1) {
                shp[(k >> 1) * 64 + lane]      = pk2(pva, ha);
                shp[(k >> 1) * 64 + lane + 32] = pk2(pvb, hb);
            } else { pva = ha; pvb = hb; }
        }
        __syncwarp();

        ull ya[8], yb[8];
        #pragma unroll
        for (int k2 = 0; k2 < 8; k2++) { ya[k2] = bd1a; yb[k2] = bd1b; }
        #pragma unroll
        for (int jb = 0; jb < 16; jb++) {
            float4 wa = *(const float4*)(s_w1 + (jb * 64 + lane) * 4);
            float4 wb = *(const float4*)(s_w1 + (jb * 64 + lane + 32) * 4);
            ull wax = dup2(wa.x), way = dup2(wa.y), waz = dup2(wa.z), waw = dup2(wa.w);
            ull wbx = dup2(wb.x), wby = dup2(wb.y), wbz = dup2(wb.z), wbw = dup2(wb.w);
            #pragma unroll
            for (int k2 = 0; k2 < 8; k2++) {
                ulonglong2 h01 = *(const ulonglong2*)(shp + k2 * 64 + jb * 4);
                ulonglong2 h23 = *(const ulonglong2*)(shp + k2 * 64 + jb * 4 + 2);
                ya[k2] = ffma2(h01.x, wax, ya[k2]);
                yb[k2] = ffma2(h01.x, wbx, yb[k2]);
                ya[k2] = ffma2(h01.y, way, ya[k2]);
                yb[k2] = ffma2(h01.y, wby, yb[k2]);
                ya[k2] = ffma2(h23.x, waz, ya[k2]);
                yb[k2] = ffma2(h23.x, wbz, yb[k2]);
                ya[k2] = ffma2(h23.y, waw, ya[k2]);
                yb[k2] = ffma2(h23.y, wbw, yb[k2]);
            }
        }

        if (NL == 2) {
            __syncwarp();
            #pragma unroll
            for (int k2 = 0; k2 < 8; k2++) {
                shp[k2 * 64 + lane]      = lky2(ya[k2]);
                shp[k2 * 64 + lane + 32] = lky2(yb[k2]);
            }
            __syncwarp();
            #pragma unroll
            for (int k2 = 0; k2 < 8; k2++) { ya[k2] = bd2a; yb[k2] = bd2b; }
            #pragma unroll
            for (int jb = 0; jb < 16; jb++) {
                float4 wa = *(const float4*)(s_w2 + (jb * 64 + lane) * 4);
                float4 wb = *(const float4*)(s_w2 + (jb * 64 + lane + 32) * 4);
                ull wax = dup2(wa.x), way = dup2(wa.y), waz = dup2(wa.z), waw = dup2(wa.w);
                ull wbx = dup2(wb.x), wby = dup2(wb.y), wbz = dup2(wb.z), wbw = dup2(wb.w);
                #pragma unroll
                for (int k2 = 0; k2 < 8; k2++) {
                    ulonglong2 h01 = *(const ulonglong2*)(shp + k2 * 64 + jb * 4);
                    ulonglong2 h23 = *(const ulonglong2*)(shp + k2 * 64 + jb * 4 + 2);
                    ya[k2] = ffma2(h01.x, wax, ya[k2]);
                    yb[k2] = ffma2(h01.x, wbx, yb[k2]);
                    ya[k2] = ffma2(h01.y, way, ya[k2]);
                    yb[k2] = ffma2(h01.y, wby, yb[k2]);
                    ya[k2] = ffma2(h23.x, waz, ya[k2]);
                    yb[k2] = ffma2(h23.x, wbz, yb[k2]);
                    ya[k2] = ffma2(h23.y, waw, ya[k2]);
                    yb[k2] = ffma2(h23.y, wbw, yb[k2]);
                }
            }
        }

        float ma = -3.0e38f, mb = -3.0e38f;
        #pragma unroll
        for (int k2 = 0; k2 < 8; k2++) {
            float u, v;
            unpk2(u, v, ya[k2]); ma = fmaxf(ma, fmaxf(u, v));
            unpk2(u, v, yb[k2]); mb = fmaxf(mb, fmaxf(u, v));
        }
        ma = leaky(ma); mb = leaky(mb);

        if (transposed) {
            out[((b * 64) + lane) * N + n] = ma;
            out[((b * 64) + lane + 32) * N + n] = mb;
        } else {
            out[q * 64 + lane] = ma;
            out[q * 64 + 32 + lane] = mb;
        }
        __syncwarp();
    }
}

// ---------------- final linear (fused both directions) ----------------
__global__ __launch_bounds__(256) void final_linear_kernel(
    const float* __restrict__ xA, const float* __restrict__ xB,
    const float* __restrict__ wA, const float* __restrict__ bA,
    const float* __restrict__ wB, const float* __restrict__ bB,
    float* __restrict__ obnA, float* __restrict__ obnB,
    float* __restrict__ ocnA, float* __restrict__ ocnB)
{
    const int dir = blockIdx.y;
    const float* x = dir ? xB : xA;
    const float* W = dir ? wB : wA;
    const float* bias = dir ? bB : bA;
    float* obn = dir ? obnB : obnA;
    float* ocn = dir ? ocnB : ocnA;

    __shared__ float s_wt[64 * 65];
    __shared__ float s_x[32 * 64];
    const int tid = threadIdx.x;
    const int q0 = blockIdx.x * 32;
    for (int i = tid; i < 64 * 64; i += 256) {
        int m = i >> 6, c = i & 63;
        s_wt[c * 65 + m] = W[i];
    }
    for (int i = tid; i < 2048; i += 256)
        s_x[i] = x[q0 * 64 + i];
    __syncthreads();

    const int m = tid & 63, grp = tid >> 6;
    float acc[8];
    const float bv = bias[m];
    #pragma unroll
    for (int t = 0; t < 8; t++) acc[t] = bv;
    #pragma unroll 4
    for (int c = 0; c < 64; c++) {
        float wv = s_wt[c * 65 + m];
        #pragma unroll
        for (int t = 0; t < 8; t++)
            acc[t] += s_x[(grp * 8 + t) * 64 + c] * wv;
    }
    #pragma unroll
    for (int t = 0; t < 8; t++) {
        int q = q0 + grp * 8 + t;
        int b = q >> 13, n = q & (N - 1);
        obn[q * 64 + m] = acc[t];
        ocn[((b * 64) + m) * N + n] = acc[t];
    }
}

// ---------------- launch ----------------
extern "C" void kernel_launch(void* const* d_in, const int* in_sizes, int n_in,
                              void* d_out, int out_size)
{
    const float* pc1     = (const float*)d_in[0];
    const float* pc2     = (const float*)d_in[1];
    const float* feat1   = (const float*)d_in[2];
    const float* feat2   = (const float*)d_in[3];
    const float* t11_w   = (const float*)d_in[4];
    const float* t11_b   = (const float*)d_in[5];
    const float* t22_w   = (const float*)d_in[6];
    const float* t22_b   = (const float*)d_in[7];
    const float* pos1_w  = (const float*)d_in[8];
    const float* pos1_b  = (const float*)d_in[9];
    const float* mlp1_w1 = (const float*)d_in[10];
    const float* mlp1_b1 = (const float*)d_in[11];
    const float* mlp1_w2 = (const float*)d_in[12];
    const float* mlp1_b2 = (const float*)d_in[13];
    const float* t1_w    = (const float*)d_in[14];
    const float* t1_b    = (const float*)d_in[15];
    const float* t2_w    = (const float*)d_in[16];
    const float* t2_b    = (const float*)d_in[17];
    const float* pos2_w  = (const float*)d_in[18];
    const float* pos2_b  = (const float*)d_in[19];
    const float* mlp2_w1 = (const float*)d_in[20];
    const float* mlp2_b1 = (const float*)d_in[21];
    float* out = (float*)d_out;

    float *q1, *q2, *r1, *r2, *c1, *c2, *f1, *f2;
    int *i12, *i21;
    cudaGetSymbolAddress((void**)&q1, g_q1);
    cudaGetSymbolAddress((void**)&q2, g_q2);
    cudaGetSymbolAddress((void**)&r1, g_r1);
    cudaGetSymbolAddress((void**)&r2, g_r2);
    cudaGetSymbolAddress((void**)&c1, g_c1);
    cudaGetSymbolAddress((void**)&c2, g_c2);
    cudaGetSymbolAddress((void**)&f1, g_f1);
    cudaGetSymbolAddress((void**)&f2, g_f2);
    cudaGetSymbolAddress((void**)&i12, g_i12);
    cudaGetSymbolAddress((void**)&i21, g_i21);

    knn_kernel<<<dim3(N / 16, BB, 2), 512>>>(pc1, pc2, i12, i21);

    transform4_kernel<<<dim3(N / 32, BB), 256>>>(feat1, feat2, t11_w, t11_b,
                                                 t22_w, t22_b, q1, q2, r1, r2);

    const size_t smem = (size_t)(8576 + 8 * 1024) * sizeof(float);
    cudaFuncSetAttribute(cross_kernel<2>, cudaFuncAttributeMaxDynamicSharedMemorySize, (int)smem);
    cudaFuncSetAttribute(cross_kernel<1>, cudaFuncAttributeMaxDynamicSharedMemorySize, (int)smem);

    cross_kernel<2><<<dim3(BB * N / 64, 2), 256, smem>>>(
        i12, i21, pc1, pc2,
        q1, q2, r1, r2,
        pos1_w, pos1_b, mlp1_w1, mlp1_b1, mlp1_w2, mlp1_b2,
        c1, c2, 0);

    final_linear_kernel<<<dim3(BB * N / 32, 2), 256>>>(
        c1, c2, t1_w, t1_b, t2_w, t2_b,
        f1, f2, out, out + (size_t)BB * 64 * N);

    cross_kernel<1><<<dim3(BB * N / 64, 1), 256, smem>>>(
        i12, i12, pc1, pc2,
        f1, f2, f1, f2,
        pos2_w, pos2_b, mlp2_w1, mlp2_b1, mlp2_w1, mlp2_b1,
        out + (size_t)2 * BB * 64 * N, out + (size_t)2 * BB * 64 * N, 1);
}